// round 2
// baseline (speedup 1.0000x reference)
#include <cuda_runtime.h>
#include <cuda_fp16.h>
#include <math.h>

#define T_DIM 2048
#define B_DIM 1024
#define A_DIM 4
#define D_DIM 128
#define P_DIM 256
#define TC    32
#define NCH   (T_DIM / TC)
#define LDW   68            // 32-bit words per tile row (136 half elems, padded)

// scratch: per (b,t,a): (s = r*a, a)
__device__ float2 g_SA[(size_t)B_DIM * T_DIM * A_DIM];

static __device__ __forceinline__ float nan0(float x) { return (x == x) ? x : 0.0f; }
static __device__ __forceinline__ float clipf(float x, float lo, float hi) {
    return fminf(fmaxf(x, lo), hi);
}

// ---------------------------------------------------------------------------
// Prep: inputs (T,B,1,9) -> g_SA[b][t][a] = (reward*action, action)
// ---------------------------------------------------------------------------
__global__ void prep_kernel(const float* __restrict__ inp) {
    int gid = blockIdx.x * blockDim.x + threadIdx.x;
    if (gid >= T_DIM * B_DIM) return;
    int b = gid % B_DIM;   // consecutive threads -> consecutive b (coalesced-ish reads)
    int t = gid / B_DIM;
    const float* row = inp + ((size_t)t * B_DIM + b) * 9;
    float2* o = g_SA + ((size_t)b * T_DIM + t) * A_DIM;
#pragma unroll
    for (int a = 0; a < A_DIM; a++) {
        float act = nan0(row[a]);
        float r   = nan0(row[4 + a]);
        o[a] = make_float2(r * act, act);   // one 32B sector per thread
    }
}

// mma.sync m16n8k16 row.col f16 -> f32
static __device__ __forceinline__ void mma16816(float* acc, const unsigned* a,
                                                unsigned b0, unsigned b1) {
    asm volatile(
        "mma.sync.aligned.m16n8k16.row.col.f32.f16.f16.f32 "
        "{%0,%1,%2,%3}, {%4,%5,%6,%7}, {%8,%9}, {%0,%1,%2,%3};\n"
        : "+f"(acc[0]), "+f"(acc[1]), "+f"(acc[2]), "+f"(acc[3])
        : "r"(a[0]), "r"(a[1]), "r"(a[2]), "r"(a[3]), "r"(b0), "r"(b1));
}

// ---------------------------------------------------------------------------
// Main: one CTA per b, 256 threads (8 warps).
// SMEM: sa_s[0,1024) beta[1024,1536) kappa[1536,2048) lpart[2048,4096)
//       Ct[4096,+34816) Hs[+34816) Qs[+34816)   total 108544 B
// ---------------------------------------------------------------------------
#define SMEM_BYTES 108544

__global__ void __launch_bounds__(256, 1) gql_main(
    const float* __restrict__ inp,
    const float* __restrict__ phi_raw,  const float* __restrict__ chi_raw,
    const float* __restrict__ beta_raw, const float* __restrict__ kappa_raw,
    const float* __restrict__ C_raw,    float* __restrict__ out) {
    extern __shared__ char sm[];
    float2*   sa_s    = (float2*)sm;
    float*    beta_s  = (float*)(sm + 1024);
    float*    kappa_s = (float*)(sm + 1536);
    float*    lpart   = (float*)(sm + 2048);
    __half*   Ct      = (__half*)(sm + 4096);
    unsigned* Ct_w    = (unsigned*)Ct;
    __half2*  Hs_h2   = (__half2*)(sm + 38912);
    unsigned* Hs_w    = (unsigned*)Hs_h2;
    __half2*  Qs_h2   = (__half2*)(sm + 73728);

    const int b    = blockIdx.x;
    const int tid  = threadIdx.x;
    const int lane = tid & 31;
    const int w    = tid >> 5;
    const int g    = lane >> 2;       // groupID
    const int tg   = lane & 3;        // threadID in group
    const int pid  = min(max((int)nan0(__ldg(inp + (size_t)b * 9 + 8)), 0), P_DIM - 1);

    // scan assignment: a = tid>>6, d-pair (d0, d0+1)
    const int aidx = tid >> 6;
    const int d2   = tid & 63;
    const int d0   = d2 * 2;

    // per-thread parameters (fp32 exact)
    float phr0 = phi_raw[pid * D_DIM + d0], phr1 = phi_raw[pid * D_DIM + d0 + 1];
    float chr0 = chi_raw[pid * D_DIM + d0], chr1 = chi_raw[pid * D_DIM + d0 + 1];
    float phi0 = clipf(1.0f / (1.0f + expf(-phr0)), 0.01f, 0.99f);
    float phi1 = clipf(1.0f / (1.0f + expf(-phr1)), 0.01f, 0.99f);
    float chi0 = clipf(1.0f / (1.0f + expf(-chr0)), 0.01f, 0.99f);
    float chi1 = clipf(1.0f / (1.0f + expf(-chr1)), 0.01f, 0.99f);
    float omp0 = 1.0f - phi0, omp1 = 1.0f - phi1;
    float omc0 = 1.0f - chi0, omc1 = 1.0f - chi1;

    if (tid < 64) {
        float b0r = beta_raw[pid * D_DIM + d0], b1r = beta_raw[pid * D_DIM + d0 + 1];
        float sp0 = fmaxf(b0r, 0.0f) + log1pf(expf(-fabsf(b0r)));
        float sp1 = fmaxf(b1r, 0.0f) + log1pf(expf(-fabsf(b1r)));
        beta_s[d0]      = clipf(sp0, 0.1f, 10.0f);
        beta_s[d0 + 1]  = clipf(sp1, 0.1f, 10.0f);
        kappa_s[d0]     = clipf(kappa_raw[pid * D_DIM + d0], -10.0f, 10.0f);
        kappa_s[d0 + 1] = clipf(kappa_raw[pid * D_DIM + d0 + 1], -10.0f, 10.0f);
    }
    // Ct[e][d] = clip(C[d][e])  (B operand, ".col": col-major K x N)
    for (int i = tid; i < D_DIM * D_DIM; i += 256) {
        int d = i >> 7, e = i & 127;
        Ct[e * 136 + d] = __float2half(clipf(C_raw[(size_t)pid * (D_DIM * D_DIM) + i],
                                             -10.0f, 10.0f));
    }
    __syncthreads();

    // warp tile: rows [mrb, mrb+64), cols [ncb, ncb+32)
    const int mrb = (w & 1) * 64;
    const int ncb = (w >> 1) * 32;

    // B fragments (C is chunk-invariant): 4 n-tiles x 8 k-steps x 2 regs
    unsigned bfr[4][8][2];
#pragma unroll
    for (int nt = 0; nt < 4; nt++) {
        const unsigned* cb = Ct_w + (ncb + nt * 8 + g) * LDW;
#pragma unroll
        for (int ks = 0; ks < 8; ks++) {
            bfr[nt][ks][0] = cb[ks * 8 + tg];
            bfr[nt][ks][1] = cb[ks * 8 + tg + 4];
        }
    }
    float2 bet[4], kap[4];
#pragma unroll
    for (int nt = 0; nt < 4; nt++) {
        int c0 = ncb + nt * 8 + tg * 2;
        bet[nt] = make_float2(beta_s[c0], beta_s[c0 + 1]);
        kap[nt] = make_float2(kappa_s[c0], kappa_s[c0 + 1]);
    }

    float q0 = 0.5f, q1 = 0.5f, h0 = 0.0f, h1 = 0.0f;
    const float2* sa_src = g_SA + (size_t)b * T_DIM * A_DIM;
    float* out_q = out + (size_t)T_DIM * B_DIM * A_DIM;
    float* out_h = out_q + B_DIM * A_DIM * D_DIM;

    for (int c = 0; c < NCH; c++) {
        if (tid < 128) sa_s[tid] = sa_src[c * 128 + tid];
        __syncthreads();

        // ---- scan phase: fp32 state, fp16 tiles ----
#pragma unroll 4
        for (int tt = 0; tt < TC; tt++) {
            float2 sa = sa_s[tt * 4 + aidx];
            float s = sa.x, a = sa.y;
            q0 = omp0 * q0 + phi0 * s;
            q1 = omp1 * q1 + phi1 * s;
            h0 = omc0 * h0 + chi0 * a;
            h1 = omc1 * h1 + chi1 * a;
            int row = tt * 4 + aidx;
            Hs_h2[row * LDW + d2] = __floats2half2_rn(h0, h1);
            Qs_h2[row * LDW + d2] = __floats2half2_rn(q0, q1);
        }
        __syncthreads();

        // ---- GEMM: U = H x C ----
        float acc[4][4][4];
#pragma unroll
        for (int mt = 0; mt < 4; mt++)
#pragma unroll
            for (int nt = 0; nt < 4; nt++)
#pragma unroll
                for (int i = 0; i < 4; i++) acc[mt][nt][i] = 0.0f;

#pragma unroll
        for (int ks = 0; ks < 8; ks++) {
            unsigned af[4][4];
            int kw = ks * 8 + tg;
#pragma unroll
            for (int mt = 0; mt < 4; mt++) {
                const unsigned* hb = Hs_w + (mrb + mt * 16 + g) * LDW;
                af[mt][0] = hb[kw];
                af[mt][1] = hb[8 * LDW + kw];
                af[mt][2] = hb[kw + 4];
                af[mt][3] = hb[8 * LDW + kw + 4];
            }
#pragma unroll
            for (int mt = 0; mt < 4; mt++)
#pragma unroll
                for (int nt = 0; nt < 4; nt++)
                    mma16816(acc[mt][nt], af[mt], bfr[nt][ks][0], bfr[nt][ks][1]);
        }

        // ---- epilogue: logit = sum_e (U+beta)*Q + sum_d kappa*H ----
#pragma unroll
        for (int mt = 0; mt < 4; mt++) {
            int r0 = mrb + mt * 16 + g;
            float p0 = 0.0f, p1 = 0.0f;
#pragma unroll
            for (int nt = 0; nt < 4; nt++) {
                int cw = (ncb >> 1) + nt * 4 + tg;
                float2 qv0 = __half22float2(Qs_h2[r0 * LDW + cw]);
                float2 qv1 = __half22float2(Qs_h2[(r0 + 8) * LDW + cw]);
                float2 hv0 = __half22float2(Hs_h2[r0 * LDW + cw]);
                float2 hv1 = __half22float2(Hs_h2[(r0 + 8) * LDW + cw]);
                p0 += (acc[mt][nt][0] + bet[nt].x) * qv0.x
                    + (acc[mt][nt][1] + bet[nt].y) * qv0.y
                    + kap[nt].x * hv0.x + kap[nt].y * hv0.y;
                p1 += (acc[mt][nt][2] + bet[nt].x) * qv1.x
                    + (acc[mt][nt][3] + bet[nt].y) * qv1.y
                    + kap[nt].x * hv1.x + kap[nt].y * hv1.y;
            }
            p0 += __shfl_xor_sync(0xffffffffu, p0, 1);
            p0 += __shfl_xor_sync(0xffffffffu, p0, 2);
            p1 += __shfl_xor_sync(0xffffffffu, p1, 1);
            p1 += __shfl_xor_sync(0xffffffffu, p1, 2);
            if (tg == 0) {
                lpart[(w >> 1) * 128 + r0]     = p0;
                lpart[(w >> 1) * 128 + r0 + 8] = p1;
            }
        }
        __syncthreads();

        if (tid < 128) {  // deterministic 4-way combine + store logits
            float lg = lpart[tid] + lpart[128 + tid] + lpart[256 + tid] + lpart[384 + tid];
            int tt = tid >> 2, a = tid & 3;
            out[((size_t)(c * TC + tt) * B_DIM + b) * A_DIM + a] = lg;
        }
    }

    // final q, h: shape (B, A, D)
    ((float2*)out_q)[(b * A_DIM + aidx) * 64 + d2] = make_float2(q0, q1);
    ((float2*)out_h)[(b * A_DIM + aidx) * 64 + d2] = make_float2(h0, h1);
}

extern "C" void kernel_launch(void* const* d_in, const int* in_sizes, int n_in,
                              void* d_out, int out_size) {
    const float* inp       = (const float*)d_in[0];
    const float* phi_raw   = (const float*)d_in[1];
    const float* chi_raw   = (const float*)d_in[2];
    const float* beta_raw  = (const float*)d_in[3];
    const float* kappa_raw = (const float*)d_in[4];
    const float* C_raw     = (const float*)d_in[5];
    float* out = (float*)d_out;

    cudaFuncSetAttribute(gql_main, cudaFuncAttributeMaxDynamicSharedMemorySize,
                         SMEM_BYTES);

    prep_kernel<<<(T_DIM * B_DIM + 255) / 256, 256>>>(inp);
    gql_main<<<B_DIM, 256, SMEM_BYTES>>>(inp, phi_raw, chi_raw, beta_raw,
                                         kappa_raw, C_raw, out);
}